// round 15
// baseline (speedup 1.0000x reference)
#include <cuda_runtime.h>
#include <cuda_fp16.h>
#include <math.h>
#include <stdint.h>

#define B_     256
#define NG_    64
#define HEADS  6
#define CH     192
#define NTOK   216
#define HD     32
#define M_POS  1331
#define PDIM   12
#define MROWS  (B_*NTOK)   // 55296
#define NBLK   (MROWS/128) // 432

// fp16 attention tiling
#define NKP     224        // keys padded to 14*16
#define KS_STRH 40         // K smem row stride in halves: conflict-free frag loads
#define VT_STRH 248        // V^T smem row stride in halves: conflict-free frag loads
#define KT16    14         // 16-key tiles
#define MT      14         // m16 query strips

// fp16 GEMM (A-resident, whole-W-block) tiling
#define AHS     200        // SMEM row stride in halves (banks 4*grp+tig, conflict-free)
#define GSMEM   ((128*AHS + 64*AHS)*2)   // 76800 B

// ---------------- scratch (all intermediates fp16) ----------------
__device__ __half   g_qh   [(size_t)MROWS*CH];
__device__ __half   g_kvh  [(size_t)MROWS*2*CH];
__device__ __half   g_atth [(size_t)MROWS*CH];
__device__ __half   g_wh   [(size_t)4*CH*CH];     // [Wqkv(3C) ; Wproj(C)] rows, half
__device__ float    g_pos  [HEADS*M_POS];
__device__ uint32_t g_mbits[(size_t)NG_*NTOK*8];  // mask bitmask: 1 = masked

__device__ __forceinline__ uint32_t pack_h2(float a, float b) {
    __half2 h = __floats2half2_rn(a, b);
    return *(uint32_t*)&h;
}

// ---------------- tiny dynamic position-bias MLP ----------------
__device__ __forceinline__ void ln12(float* t, const float* g, const float* b) {
    float mu = 0.f;
    #pragma unroll
    for (int i = 0; i < PDIM; i++) mu += t[i];
    mu *= (1.f/PDIM);
    float v = 0.f;
    #pragma unroll
    for (int i = 0; i < PDIM; i++) { float d = t[i]-mu; v += d*d; }
    v *= (1.f/PDIM);
    float inv = rsqrtf(v + 1e-5f);
    #pragma unroll
    for (int i = 0; i < PDIM; i++) t[i] = (t[i]-mu)*inv*g[i] + b[i];
}

__global__ void pos_mlp_kernel(
    const float* __restrict__ ppw, const float* __restrict__ ppb,
    const float* __restrict__ g1,  const float* __restrict__ be1,
    const float* __restrict__ w1,  const float* __restrict__ b1,
    const float* __restrict__ g2,  const float* __restrict__ be2,
    const float* __restrict__ w2,  const float* __restrict__ b2,
    const float* __restrict__ g3,  const float* __restrict__ be3,
    const float* __restrict__ w3,  const float* __restrict__ b3)
{
    int m = blockIdx.x*blockDim.x + threadIdx.x;
    if (m >= M_POS) return;
    float c0 = (float)(m/121 - 5);
    float c1 = (float)((m/11)%11 - 5);
    float c2 = (float)(m%11 - 5);
    float t[PDIM], u[PDIM];
    #pragma unroll
    for (int i = 0; i < PDIM; i++)
        t[i] = ppw[i*3+0]*c0 + ppw[i*3+1]*c1 + ppw[i*3+2]*c2 + ppb[i];
    ln12(t, g1, be1);
    #pragma unroll
    for (int i = 0; i < PDIM; i++) {
        float acc = b1[i];
        #pragma unroll
        for (int j = 0; j < PDIM; j++) acc += w1[i*PDIM+j]*fmaxf(t[j],0.f);
        u[i] = acc;
    }
    ln12(u, g2, be2);
    #pragma unroll
    for (int i = 0; i < PDIM; i++) {
        float acc = b2[i];
        #pragma unroll
        for (int j = 0; j < PDIM; j++) acc += w2[i*PDIM+j]*fmaxf(u[j],0.f);
        t[i] = acc;
    }
    ln12(t, g3, be3);
    #pragma unroll
    for (int h = 0; h < HEADS; h++) {
        float acc = b3[h];
        #pragma unroll
        for (int j = 0; j < PDIM; j++) acc += w3[h*PDIM+j]*fmaxf(t[j],0.f);
        g_pos[h*M_POS + m] = acc;
    }
}

// ---------------- one-shot weight conversion fp32 -> fp16 ----------------
__global__ void conv_w_kernel(const float* __restrict__ Wqkv,
                              const float* __restrict__ Wproj)
{
    int i = (blockIdx.x*256 + threadIdx.x) * 4;
    const int QKV = 3*CH*CH;
    const int TOT = 4*CH*CH;
    if (i >= TOT) return;
    float4 v = (i < QKV) ? *(const float4*)(Wqkv + i)
                         : *(const float4*)(Wproj + (i - QKV));
    uint2 p = make_uint2(pack_h2(v.x, v.y), pack_h2(v.z, v.w));
    *(uint2*)&g_wh[i] = p;
}

// ---------------- one-shot mask -> bitmask ----------------
__global__ void mask_bits_kernel(const float* __restrict__ mask)
{
    int row  = (blockIdx.x*256 + threadIdx.x) >> 5;   // g*NTOK + n
    int lane = threadIdx.x & 31;
    if (row >= NG_*NTOK) return;
    const float* r = mask + (size_t)row*NTOK;
    #pragma unroll
    for (int i = 0; i < 7; i++) {
        int m = i*32 + lane;
        bool bit = (m < NTOK) && (r[m] < -1.f);
        uint32_t wv = __ballot_sync(0xffffffffu, bit);
        if (lane == 0) g_mbits[(size_t)row*8 + i] = wv;
    }
}

// ---------------- FP16 GEMM body: A-resident, whole-W-block, reg prefetch ----------------
template<bool A_HALF, bool OUT_HALF>
__device__ __forceinline__
void gemm_body(const void* __restrict__ Ain, const __half* __restrict__ Wh,
               const float* __restrict__ bias, void* __restrict__ Cout,
               int Ndim, int m0)
{
    extern __shared__ __half sg[];
    __half* Ah = sg;                 // [128][AHS]
    __half* Ws = Ah + 128*AHS;       // [64][AHS]

    int tid  = threadIdx.x;
    int w    = tid >> 5, lane = tid & 31;
    int grp  = lane >> 2, tig = lane & 3;
    int wm   = (w >> 1) * 32;
    int wn   = (w & 1) * 32;

    if (A_HALF) {
        const __half* Af = (const __half*)Ain + (size_t)m0*CH;
        #pragma unroll
        for (int i = 0; i < 24; i++) {
            int idx = i*256 + tid;
            int row = idx/48, c4 = idx%48;
            uint2 v = *(const uint2*)(Af + (size_t)row*CH + c4*4);
            *(uint2*)&Ah[row*AHS + c4*4] = v;
        }
    } else {
        const float* Af = (const float*)Ain + (size_t)m0*CH;
        #pragma unroll
        for (int i = 0; i < 24; i++) {
            int idx = i*256 + tid;
            int row = idx/48, c4 = idx%48;
            float4 v = *(const float4*)(Af + (size_t)row*CH + c4*4);
            uint2 p = make_uint2(pack_h2(v.x, v.y), pack_h2(v.z, v.w));
            *(uint2*)&Ah[row*AHS + c4*4] = p;
        }
    }

    const uint32_t* Ahw = (const uint32_t*)Ah;
    uint32_t* Wsw = (uint32_t*)Ws;
    int nbc = Ndim >> 6;

    uint4 wR[6];
    #pragma unroll
    for (int i = 0; i < 6; i++) {
        int idx = i*256 + tid;
        int row = idx/24, c8 = idx%24;
        wR[i] = *(const uint4*)(Wh + (size_t)row*CH + c8*8);
    }

    for (int nb = 0; nb < nbc; nb++) {
        #pragma unroll
        for (int i = 0; i < 6; i++) {
            int idx = i*256 + tid;
            int row = idx/24, c8 = idx%24;
            *(uint4*)&Ws[row*AHS + c8*8] = wR[i];
        }
        __syncthreads();

        if (nb + 1 < nbc) {
            const __half* Wb = Wh + (size_t)(nb+1)*64*CH;
            #pragma unroll
            for (int i = 0; i < 6; i++) {
                int idx = i*256 + tid;
                int row = idx/24, c8 = idx%24;
                wR[i] = *(const uint4*)(Wb + (size_t)row*CH + c8*8);
            }
        }

        float acc[2][4][4];
        #pragma unroll
        for (int i = 0; i < 2; i++)
            #pragma unroll
            for (int j = 0; j < 4; j++)
                #pragma unroll
                for (int c = 0; c < 4; c++) acc[i][j][c] = 0.f;

        #pragma unroll
        for (int st = 0; st < 12; st++) {
            int ko = st*8;
            uint32_t af[2][4], bf[4][2];
            #pragma unroll
            for (int mf = 0; mf < 2; mf++) {
                int r = wm + mf*16 + grp;
                af[mf][0] = Ahw[(r    )*(AHS/2) + ko + tig];
                af[mf][1] = Ahw[(r + 8)*(AHS/2) + ko + tig];
                af[mf][2] = Ahw[(r    )*(AHS/2) + ko + tig + 4];
                af[mf][3] = Ahw[(r + 8)*(AHS/2) + ko + tig + 4];
            }
            #pragma unroll
            for (int nf = 0; nf < 4; nf++) {
                int n = wn + nf*8 + grp;
                bf[nf][0] = Wsw[n*(AHS/2) + ko + tig];
                bf[nf][1] = Wsw[n*(AHS/2) + ko + tig + 4];
            }
            #pragma unroll
            for (int mf = 0; mf < 2; mf++)
                #pragma unroll
                for (int nf = 0; nf < 4; nf++) {
                    asm volatile(
                        "mma.sync.aligned.m16n8k16.row.col.f32.f16.f16.f32 "
                        "{%0,%1,%2,%3}, {%4,%5,%6,%7}, {%8,%9}, {%0,%1,%2,%3};"
                        : "+f"(acc[mf][nf][0]), "+f"(acc[mf][nf][1]),
                          "+f"(acc[mf][nf][2]), "+f"(acc[mf][nf][3])
                        : "r"(af[mf][0]), "r"(af[mf][1]), "r"(af[mf][2]), "r"(af[mf][3]),
                          "r"(bf[nf][0]), "r"(bf[nf][1]));
                }
        }

        int n0 = nb*64;
        #pragma unroll
        for (int mf = 0; mf < 2; mf++) {
            #pragma unroll
            for (int nf = 0; nf < 4; nf++) {
                int col = n0 + wn + nf*8 + 2*tig;
                float bx = bias[col], by = bias[col+1];
                int r0 = m0 + wm + mf*16 + grp;
                if (OUT_HALF) {
                    __half* Co = (__half*)Cout;
                    *(uint32_t*)&Co[(size_t)r0*Ndim + col] =
                        pack_h2(acc[mf][nf][0] + bx, acc[mf][nf][1] + by);
                    *(uint32_t*)&Co[(size_t)(r0+8)*Ndim + col] =
                        pack_h2(acc[mf][nf][2] + bx, acc[mf][nf][3] + by);
                } else {
                    float* Co = (float*)Cout;
                    *(float2*)&Co[(size_t)r0*Ndim + col] =
                        make_float2(acc[mf][nf][0] + bx, acc[mf][nf][1] + by);
                    *(float2*)&Co[(size_t)(r0+8)*Ndim + col] =
                        make_float2(acc[mf][nf][2] + bx, acc[mf][nf][3] + by);
                }
            }
        }
        __syncthreads();
    }
}

// merged Q + KV GEMM: blocks [0,NBLK) do Q from x, [NBLK,2*NBLK) do KV from y
__global__ __launch_bounds__(256)
void gemm_qkv_kernel(const float* __restrict__ x, const float* __restrict__ y,
                     const float* __restrict__ bqkv)
{
    int bi = blockIdx.x;
    if (bi < NBLK) {
        gemm_body<false, true>(x, g_wh, bqkv, g_qh, CH, bi*128);
    } else {
        gemm_body<false, true>(y, g_wh + (size_t)CH*CH, bqkv + CH,
                               g_kvh, 2*CH, (bi - NBLK)*128);
    }
}

// projection GEMM
__global__ __launch_bounds__(256)
void gemm_proj_kernel(const float* __restrict__ bproj, float* __restrict__ out)
{
    gemm_body<true, false>(g_atth, g_wh + (size_t)3*CH*CH, bproj, out,
                           CH, blockIdx.x*128);
}

// ---------------- fp16 tensor-core fused attention (bitmask, online softmax) ----------------
// 224 threads: 7 warps x exactly 2 strips. Paired pos LUT; mask as bits. (R12 version)
__global__ __launch_bounds__(224)
void attn_tc_kernel()
{
    extern __shared__ __half smh[];
    __half* Ksh  = smh;                          // [224][40] half
    __half* Vth  = Ksh + NKP*KS_STRH;            // [32][248] half (V^T)
    float2* poshd = (float2*)(Vth + 32*VT_STRH); // [1331] (pos[a], pos[a-1])
    short*  midv  = (short*)(poshd + M_POS);     // [216] pid3 LUT

    int bh = blockIdx.x;
    int b  = bh / HEADS, h = bh % HEADS;
    int g  = b & (NG_-1);
    int tid = threadIdx.x;
    int w = tid >> 5, lane = tid & 31;
    int grp = lane >> 2, tig = lane & 3;

    const __half* kvbh = g_kvh + (size_t)b*NTOK*(2*CH);
    for (int e = tid; e < NKP*16; e += 224) {
        int m = e >> 4, d = (e & 15)*2;
        uint32_t ku = 0u, vu = 0u;
        if (m < NTOK) {
            ku = *(const uint32_t*)&kvbh[(size_t)m*(2*CH) + h*32 + d];
            vu = *(const uint32_t*)&kvbh[(size_t)m*(2*CH) + CH + h*32 + d];
        }
        *(uint32_t*)&Ksh[m*KS_STRH + d] = ku;
        __half2 vh = *(__half2*)&vu;
        Vth[(d    )*VT_STRH + m] = vh.x;
        Vth[(d + 1)*VT_STRH + m] = vh.y;
    }
    for (int e = tid; e < M_POS; e += 224) {
        float cur = g_pos[h*M_POS + e];
        float prv = (e > 0) ? g_pos[h*M_POS + e - 1] : 0.f;
        poshd[e] = make_float2(cur, prv);
    }
    for (int e = tid; e < NTOK; e += 224)
        midv[e] = (short)((e/36)*121 + ((e/6)%6)*11 + (e%6));
    __syncthreads();

    const __half* qbh = g_qh + (size_t)b*NTOK*CH + h*32;
    __half* obh = g_atth + (size_t)b*NTOK*CH + h*32;
    const uint32_t* mbase = g_mbits + (size_t)g*NTOK*8;
    const float scale = 0.17677669529663687f;  // 32^-0.5

    for (int strip = w; strip < MT; strip += 7) {
        int n0 = strip*16;
        int ra = n0 + grp, rb = ra + 8;
        int ra_c = min(ra, NTOK-1), rb_c = min(rb, NTOK-1);

        // Q A-frags: direct half2 loads
        uint32_t aq[2][4];
        const __half* qa = qbh + (size_t)ra_c*CH;
        const __half* qB = qbh + (size_t)rb_c*CH;
        #pragma unroll
        for (int c = 0; c < 2; c++) {
            aq[c][0] = *(const uint32_t*)&qa[c*16 + 2*tig];
            aq[c][1] = *(const uint32_t*)&qB[c*16 + 2*tig];
            aq[c][2] = *(const uint32_t*)&qa[c*16 + 2*tig + 8];
            aq[c][3] = *(const uint32_t*)&qB[c*16 + 2*tig + 8];
        }

        // row bitmasks (7 words each, broadcast loads)
        uint32_t mba[7], mbb[7];
        {
            const uint32_t* ma = mbase + (size_t)ra_c*8;
            const uint32_t* mb = mbase + (size_t)rb_c*8;
            #pragma unroll
            for (int i = 0; i < 7; i++) { mba[i] = ma[i]; mbb[i] = mb[i]; }
        }

        int nida = midv[ra_c], nidb = midv[rb_c];

        float o[4][4];
        #pragma unroll
        for (int dt = 0; dt < 4; dt++)
            #pragma unroll
            for (int c = 0; c < 4; c++) o[dt][c] = 0.f;
        float sa = 0.f, sb = 0.f;

        #pragma unroll 2
        for (int kt = 0; kt < KT16; kt++) {
            // S tiles = Q K^T
            float s0c[4] = {0.f,0.f,0.f,0.f};
            float s1c[4] = {0.f,0.f,0.f,0.f};
            int key0 = kt*16 + grp;
            #pragma unroll
            for (int c = 0; c < 2; c++) {
                uint32_t b0 = *(const uint32_t*)&Ksh[(key0    )*KS_STRH + c*16 + 2*tig];
                uint32_t b1 = *(const uint32_t*)&Ksh[(key0    )*KS_STRH + c*16 + 2*tig + 8];
                uint32_t d0 = *(const uint32_t*)&Ksh[(key0 + 8)*KS_STRH + c*16 + 2*tig];
                uint32_t d1 = *(const uint32_t*)&Ksh[(key0 + 8)*KS_STRH + c*16 + 2*tig + 8];
                asm volatile(
                    "mma.sync.aligned.m16n8k16.row.col.f32.f16.f16.f32 "
                    "{%0,%1,%2,%3}, {%4,%5,%6,%7}, {%8,%9}, {%0,%1,%2,%3};"
                    : "+f"(s0c[0]), "+f"(s0c[1]), "+f"(s0c[2]), "+f"(s0c[3])
                    : "r"(aq[c][0]), "r"(aq[c][1]), "r"(aq[c][2]), "r"(aq[c][3]),
                      "r"(b0), "r"(b1));
                asm volatile(
                    "mma.sync.aligned.m16n8k16.row.col.f32.f16.f16.f32 "
                    "{%0,%1,%2,%3}, {%4,%5,%6,%7}, {%8,%9}, {%0,%1,%2,%3};"
                    : "+f"(s1c[0]), "+f"(s1c[1]), "+f"(s1c[2]), "+f"(s1c[3])
                    : "r"(aq[c][0]), "r"(aq[c][1]), "r"(aq[c][2]), "r"(aq[c][3]),
                      "r"(d0), "r"(d1));
            }

            // mask bits for this kt (compile-time word index under unroll)
            uint32_t wa = mba[kt >> 1] >> ((kt & 1)*16 + 2*tig);
            uint32_t wb = mbb[kt >> 1] >> ((kt & 1)*16 + 2*tig);

            // bias(paired LUT) + bitmask + exp, accumulate row sums, pack P frags
            uint32_t pa0, pa1, pa2, pa3;
            {
                int m0 = kt*16 + 2*tig;
                int mid0 = midv[m0];
                float2 Pa = poshd[nida - mid0 + 665];   // .x even m, .y odd m
                float2 Pb = poshd[nidb - mid0 + 665];
                float p00 = (wa & 1u)   ? 0.f : __expf(s0c[0]*scale + Pa.x);
                float p01 = (wa & 2u)   ? 0.f : __expf(s0c[1]*scale + Pa.y);
                float p02 = (wb & 1u)   ? 0.f : __expf(s0c[2]*scale + Pb.x);
                float p03 = (wb & 2u)   ? 0.f : __expf(s0c[3]*scale + Pb.y);
                sa += p00 + p01;
                sb += p02 + p03;
                pa0 = pack_h2(p00, p01);
                pa1 = pack_h2(p02, p03);
            }
            if (kt < KT16-1) {
                int m1 = kt*16 + 8 + 2*tig;
                int mid1 = midv[m1];
                float2 Pa = poshd[nida - mid1 + 665];
                float2 Pb = poshd[nidb - mid1 + 665];
                float p10 = (wa & 0x100u) ? 0.f : __expf(s1c[0]*scale + Pa.x);
                float p11 = (wa & 0x200u) ? 0.f : __expf(s1c[1]*scale + Pa.y);
                float p12 = (wb & 0x100u) ? 0.f : __expf(s1c[2]*scale + Pb.x);
                float p13 = (wb & 0x200u) ? 0.f : __expf(s1c[3]*scale + Pb.y);
                sa += p10 + p11;
                sb += p12 + p13;
                pa2 = pack_h2(p10, p11);
                pa3 = pack_h2(p12, p13);
            } else {
                pa2 = 0u; pa3 = 0u;
            }

            // O += P V
            #pragma unroll
            for (int dt = 0; dt < 4; dt++) {
                uint32_t b0 = *(const uint32_t*)&Vth[(dt*8 + grp)*VT_STRH + kt*16 + 2*tig];
                uint32_t b1 = *(const uint32_t*)&Vth[(dt*8 + grp)*VT_STRH + kt*16 + 2*tig + 8];
                asm volatile(
                    "mma.sync.aligned.m16n8k16.row.col.f32.f16.f16.f32 "
                    "{%0,%1,%2,%3}, {%4,%5,%6,%7}, {%8,%9}, {%0,%1,%2,%3};"
                    : "+f"(o[dt][0]), "+f"(o[dt][1]), "+f"(o[dt][2]), "+f"(o[dt][3])
                    : "r"(pa0), "r"(pa1), "r"(pa2), "r"(pa3),
                      "r"(b0), "r"(b1));
            }
        }

        sa += __shfl_xor_sync(0xffffffffu, sa, 1);
        sa += __shfl_xor_sync(0xffffffffu, sa, 2);
        sb += __shfl_xor_sync(0xffffffffu, sb, 1);
        sb += __shfl_xor_sync(0xffffffffu, sb, 2);
        float inva = 1.f / sa, invb = 1.f / sb;

        #pragma unroll
        for (int dt = 0; dt < 4; dt++) {
            int d = dt*8 + 2*tig;
            *(uint32_t*)&obh[(size_t)ra*CH + d] =
                pack_h2(o[dt][0]*inva, o[dt][1]*inva);
            if (rb < NTOK)
                *(uint32_t*)&obh[(size_t)rb*CH + d] =
                    pack_h2(o[dt][2]*invb, o[dt][3]*invb);
        }
    }
}

// ---------------- launch ----------------
extern "C" void kernel_launch(void* const* d_in, const int* in_sizes, int n_in,
                              void* d_out, int out_size)
{
    const float* x     = (const float*)d_in[0];
    const float* y     = (const float*)d_in[1];
    const float* mask  = (const float*)d_in[2];
    const float* Wqkv  = (const float*)d_in[3];
    const float* bqkv  = (const float*)d_in[4];
    const float* Wproj = (const float*)d_in[5];
    const float* bproj = (const float*)d_in[6];
    const float* ppw   = (const float*)d_in[7];
    const float* ppb   = (const float*)d_in[8];
    const float* g1    = (const float*)d_in[9];
    const float* be1   = (const float*)d_in[10];
    const float* w1    = (const float*)d_in[11];
    const float* b1    = (const float*)d_in[12];
    const float* g2    = (const float*)d_in[13];
    const float* be2   = (const float*)d_in[14];
    const float* w2    = (const float*)d_in[15];
    const float* b2    = (const float*)d_in[16];
    const float* g3    = (const float*)d_in[17];
    const float* be3   = (const float*)d_in[18];
    const float* w3    = (const float*)d_in[19];
    const float* b3    = (const float*)d_in[20];
    float* out = (float*)d_out;

    pos_mlp_kernel<<<(M_POS+255)/256, 256>>>(ppw, ppb, g1, be1, w1, b1,
                                             g2, be2, w2, b2, g3, be3, w3, b3);
    conv_w_kernel<<<(4*CH*CH/4 + 255)/256, 256>>>(Wqkv, Wproj);
    mask_bits_kernel<<<(NG_*NTOK*32 + 255)/256, 256>>>(mask);

    cudaFuncSetAttribute(gemm_qkv_kernel,
                         cudaFuncAttributeMaxDynamicSharedMemorySize, GSMEM);
    cudaFuncSetAttribute(gemm_proj_kernel,
                         cudaFuncAttributeMaxDynamicSharedMemorySize, GSMEM);

    // merged Q + KV GEMM (Q from x, KV from y) -> half
    gemm_qkv_kernel<<<2*NBLK, 256, GSMEM>>>(x, y, bqkv);

    // fused attention (half in, half out; mask via bitmask)
    {
        size_t smem = (size_t)(NKP*KS_STRH + 32*VT_STRH)*2
                    + (size_t)M_POS*8 + (size_t)NTOK*2;
        cudaFuncSetAttribute(attn_tc_kernel, cudaFuncAttributeMaxDynamicSharedMemorySize, (int)smem);
        attn_tc_kernel<<<B_*HEADS, 224, smem>>>();
    }

    // out = att @ Wproj^T + bproj  (half A, float out)
    gemm_proj_kernel<<<NBLK, 256, GSMEM>>>(bproj, out);
}

// round 16
// speedup vs baseline: 1.6214x; 1.6214x over previous
#include <cuda_runtime.h>
#include <cuda_fp16.h>
#include <math.h>
#include <stdint.h>

#define B_     256
#define NG_    64
#define HEADS  6
#define CH     192
#define NTOK   216
#define HD     32
#define M_POS  1331
#define PDIM   12
#define MROWS  (B_*NTOK)   // 55296
#define NBLK   (MROWS/128) // 432

// fp16 attention tiling
#define NKP     224        // keys padded to 14*16
#define KS_STRH 40         // K smem row stride in halves: conflict-free frag loads
#define VT_STRH 248        // V^T smem row stride in halves: conflict-free frag loads
#define KT16    14         // 16-key tiles
#define MT      14         // m16 query strips

// fp16 GEMM (A-resident, whole-W-block) tiling
#define AHS     200        // SMEM row stride in halves (banks 4*grp+tig, conflict-free)
#define GSMEM   ((128*AHS + 64*AHS)*2)   // 76800 B

// prep kernel block partition
#define PREP_MB 1728       // mask_bits blocks (64*216 rows * 32 lanes / 256)
#define PREP_CB 144        // conv_w blocks (4*192*192/4/256)
#define PREP_PB 6          // pos_mlp blocks

// ---------------- scratch (all intermediates fp16) ----------------
__device__ __half   g_qh   [(size_t)MROWS*CH];
__device__ __half   g_kvh  [(size_t)MROWS*2*CH];
__device__ __half   g_atth [(size_t)MROWS*CH];
__device__ __half   g_wh   [(size_t)4*CH*CH];     // [Wqkv(3C) ; Wproj(C)] rows, half
__device__ float    g_pos  [HEADS*M_POS];
__device__ uint32_t g_mbits[(size_t)NG_*NTOK*8];  // mask bitmask: 1 = masked

__device__ __forceinline__ uint32_t pack_h2(float a, float b) {
    __half2 h = __floats2half2_rn(a, b);
    return *(uint32_t*)&h;
}

// ---------------- tiny dynamic position-bias MLP helper ----------------
__device__ __forceinline__ void ln12(float* t, const float* g, const float* b) {
    float mu = 0.f;
    #pragma unroll
    for (int i = 0; i < PDIM; i++) mu += t[i];
    mu *= (1.f/PDIM);
    float v = 0.f;
    #pragma unroll
    for (int i = 0; i < PDIM; i++) { float d = t[i]-mu; v += d*d; }
    v *= (1.f/PDIM);
    float inv = rsqrtf(v + 1e-5f);
    #pragma unroll
    for (int i = 0; i < PDIM; i++) t[i] = (t[i]-mu)*inv*g[i] + b[i];
}

// ---------------- merged prep kernel: mask_bits | conv_w | pos_mlp ----------------
__global__ void prep_kernel(
    const float* __restrict__ mask,
    const float* __restrict__ Wqkv, const float* __restrict__ Wproj,
    const float* __restrict__ ppw, const float* __restrict__ ppb,
    const float* __restrict__ g1,  const float* __restrict__ be1,
    const float* __restrict__ w1,  const float* __restrict__ b1,
    const float* __restrict__ g2,  const float* __restrict__ be2,
    const float* __restrict__ w2,  const float* __restrict__ b2,
    const float* __restrict__ g3,  const float* __restrict__ be3,
    const float* __restrict__ w3,  const float* __restrict__ b3)
{
    int bi = blockIdx.x;
    if (bi < PREP_MB) {
        // ---- mask -> bitmask ----
        int row  = (bi*256 + (int)threadIdx.x) >> 5;   // g*NTOK + n
        int lane = threadIdx.x & 31;
        if (row >= NG_*NTOK) return;
        const float* r = mask + (size_t)row*NTOK;
        #pragma unroll
        for (int i = 0; i < 7; i++) {
            int m = i*32 + lane;
            bool bit = (m < NTOK) && (r[m] < -1.f);
            uint32_t wv = __ballot_sync(0xffffffffu, bit);
            if (lane == 0) g_mbits[(size_t)row*8 + i] = wv;
        }
    } else if (bi < PREP_MB + PREP_CB) {
        // ---- weights fp32 -> fp16 ----
        int i = ((bi - PREP_MB)*256 + (int)threadIdx.x) * 4;
        const int QKV = 3*CH*CH;
        const int TOT = 4*CH*CH;
        if (i >= TOT) return;
        float4 v = (i < QKV) ? *(const float4*)(Wqkv + i)
                             : *(const float4*)(Wproj + (i - QKV));
        uint2 p = make_uint2(pack_h2(v.x, v.y), pack_h2(v.z, v.w));
        *(uint2*)&g_wh[i] = p;
    } else {
        // ---- position-bias MLP ----
        int m = (bi - PREP_MB - PREP_CB)*256 + (int)threadIdx.x;
        if (m >= M_POS) return;
        float c0 = (float)(m/121 - 5);
        float c1 = (float)((m/11)%11 - 5);
        float c2 = (float)(m%11 - 5);
        float t[PDIM], u[PDIM];
        #pragma unroll
        for (int i = 0; i < PDIM; i++)
            t[i] = ppw[i*3+0]*c0 + ppw[i*3+1]*c1 + ppw[i*3+2]*c2 + ppb[i];
        ln12(t, g1, be1);
        #pragma unroll
        for (int i = 0; i < PDIM; i++) {
            float acc = b1[i];
            #pragma unroll
            for (int j = 0; j < PDIM; j++) acc += w1[i*PDIM+j]*fmaxf(t[j],0.f);
            u[i] = acc;
        }
        ln12(u, g2, be2);
        #pragma unroll
        for (int i = 0; i < PDIM; i++) {
            float acc = b2[i];
            #pragma unroll
            for (int j = 0; j < PDIM; j++) acc += w2[i*PDIM+j]*fmaxf(u[j],0.f);
            t[i] = acc;
        }
        ln12(t, g3, be3);
        #pragma unroll
        for (int h = 0; h < HEADS; h++) {
            float acc = b3[h];
            #pragma unroll
            for (int j = 0; j < PDIM; j++) acc += w3[h*PDIM+j]*fmaxf(t[j],0.f);
            g_pos[h*M_POS + m] = acc;
        }
    }
}

// ---------------- FP16 tensor-core GEMM: A-resident, whole-W-block, reg prefetch ----------------
template<bool A_HALF, bool OUT_HALF>
__global__ __launch_bounds__(256)
void gemm_f16_big(const void* __restrict__ Ain, const __half* __restrict__ Wh,
                  const float* __restrict__ bias, void* __restrict__ Cout, int Ndim)
{
    extern __shared__ __half sg[];
    __half* Ah = sg;                 // [128][AHS]
    __half* Ws = Ah + 128*AHS;       // [64][AHS]

    int tid  = threadIdx.x;
    int w    = tid >> 5, lane = tid & 31;
    int grp  = lane >> 2, tig = lane & 3;
    int wm   = (w >> 1) * 32;
    int wn   = (w & 1) * 32;
    int m0   = blockIdx.x * 128;

    if (A_HALF) {
        const __half* Af = (const __half*)Ain + (size_t)m0*CH;
        #pragma unroll
        for (int i = 0; i < 24; i++) {
            int idx = i*256 + tid;
            int row = idx/48, c4 = idx%48;
            uint2 v = *(const uint2*)(Af + (size_t)row*CH + c4*4);
            *(uint2*)&Ah[row*AHS + c4*4] = v;
        }
    } else {
        const float* Af = (const float*)Ain + (size_t)m0*CH;
        #pragma unroll
        for (int i = 0; i < 24; i++) {
            int idx = i*256 + tid;
            int row = idx/48, c4 = idx%48;
            float4 v = *(const float4*)(Af + (size_t)row*CH + c4*4);
            uint2 p = make_uint2(pack_h2(v.x, v.y), pack_h2(v.z, v.w));
            *(uint2*)&Ah[row*AHS + c4*4] = p;
        }
    }

    const uint32_t* Ahw = (const uint32_t*)Ah;
    uint32_t* Wsw = (uint32_t*)Ws;
    int nbc = Ndim >> 6;

    uint4 wR[6];
    #pragma unroll
    for (int i = 0; i < 6; i++) {
        int idx = i*256 + tid;
        int row = idx/24, c8 = idx%24;
        wR[i] = *(const uint4*)(Wh + (size_t)row*CH + c8*8);
    }

    for (int nb = 0; nb < nbc; nb++) {
        #pragma unroll
        for (int i = 0; i < 6; i++) {
            int idx = i*256 + tid;
            int row = idx/24, c8 = idx%24;
            *(uint4*)&Ws[row*AHS + c8*8] = wR[i];
        }
        __syncthreads();

        if (nb + 1 < nbc) {
            const __half* Wb = Wh + (size_t)(nb+1)*64*CH;
            #pragma unroll
            for (int i = 0; i < 6; i++) {
                int idx = i*256 + tid;
                int row = idx/24, c8 = idx%24;
                wR[i] = *(const uint4*)(Wb + (size_t)row*CH + c8*8);
            }
        }

        float acc[2][4][4];
        #pragma unroll
        for (int i = 0; i < 2; i++)
            #pragma unroll
            for (int j = 0; j < 4; j++)
                #pragma unroll
                for (int c = 0; c < 4; c++) acc[i][j][c] = 0.f;

        #pragma unroll
        for (int st = 0; st < 12; st++) {
            int ko = st*8;
            uint32_t af[2][4], bf[4][2];
            #pragma unroll
            for (int mf = 0; mf < 2; mf++) {
                int r = wm + mf*16 + grp;
                af[mf][0] = Ahw[(r    )*(AHS/2) + ko + tig];
                af[mf][1] = Ahw[(r + 8)*(AHS/2) + ko + tig];
                af[mf][2] = Ahw[(r    )*(AHS/2) + ko + tig + 4];
                af[mf][3] = Ahw[(r + 8)*(AHS/2) + ko + tig + 4];
            }
            #pragma unroll
            for (int nf = 0; nf < 4; nf++) {
                int n = wn + nf*8 + grp;
                bf[nf][0] = Wsw[n*(AHS/2) + ko + tig];
                bf[nf][1] = Wsw[n*(AHS/2) + ko + tig + 4];
            }
            #pragma unroll
            for (int mf = 0; mf < 2; mf++)
                #pragma unroll
                for (int nf = 0; nf < 4; nf++) {
                    asm volatile(
                        "mma.sync.aligned.m16n8k16.row.col.f32.f16.f16.f32 "
                        "{%0,%1,%2,%3}, {%4,%5,%6,%7}, {%8,%9}, {%0,%1,%2,%3};"
                        : "+f"(acc[mf][nf][0]), "+f"(acc[mf][nf][1]),
                          "+f"(acc[mf][nf][2]), "+f"(acc[mf][nf][3])
                        : "r"(af[mf][0]), "r"(af[mf][1]), "r"(af[mf][2]), "r"(af[mf][3]),
                          "r"(bf[nf][0]), "r"(bf[nf][1]));
                }
        }

        int n0 = nb*64;
        #pragma unroll
        for (int mf = 0; mf < 2; mf++) {
            #pragma unroll
            for (int nf = 0; nf < 4; nf++) {
                int col = n0 + wn + nf*8 + 2*tig;
                float bx = bias[col], by = bias[col+1];
                int r0 = m0 + wm + mf*16 + grp;
                if (OUT_HALF) {
                    __half* Co = (__half*)Cout;
                    *(uint32_t*)&Co[(size_t)r0*Ndim + col] =
                        pack_h2(acc[mf][nf][0] + bx, acc[mf][nf][1] + by);
                    *(uint32_t*)&Co[(size_t)(r0+8)*Ndim + col] =
                        pack_h2(acc[mf][nf][2] + bx, acc[mf][nf][3] + by);
                } else {
                    float* Co = (float*)Cout;
                    *(float2*)&Co[(size_t)r0*Ndim + col] =
                        make_float2(acc[mf][nf][0] + bx, acc[mf][nf][1] + by);
                    *(float2*)&Co[(size_t)(r0+8)*Ndim + col] =
                        make_float2(acc[mf][nf][2] + bx, acc[mf][nf][3] + by);
                }
            }
        }
        __syncthreads();
    }
}

// ---------------- fp16 tensor-core fused attention (bitmask, online softmax) ----------------
// 224 threads: 7 warps x exactly 2 strips. Paired pos LUT; mask as bits. (R12 version)
__global__ __launch_bounds__(224)
void attn_tc_kernel()
{
    extern __shared__ __half smh[];
    __half* Ksh  = smh;                          // [224][40] half
    __half* Vth  = Ksh + NKP*KS_STRH;            // [32][248] half (V^T)
    float2* poshd = (float2*)(Vth + 32*VT_STRH); // [1331] (pos[a], pos[a-1])
    short*  midv  = (short*)(poshd + M_POS);     // [216] pid3 LUT

    int bh = blockIdx.x;
    int b  = bh / HEADS, h = bh % HEADS;
    int g  = b & (NG_-1);
    int tid = threadIdx.x;
    int w = tid >> 5, lane = tid & 31;
    int grp = lane >> 2, tig = lane & 3;

    const __half* kvbh = g_kvh + (size_t)b*NTOK*(2*CH);
    for (int e = tid; e < NKP*16; e += 224) {
        int m = e >> 4, d = (e & 15)*2;
        uint32_t ku = 0u, vu = 0u;
        if (m < NTOK) {
            ku = *(const uint32_t*)&kvbh[(size_t)m*(2*CH) + h*32 + d];
            vu = *(const uint32_t*)&kvbh[(size_t)m*(2*CH) + CH + h*32 + d];
        }
        *(uint32_t*)&Ksh[m*KS_STRH + d] = ku;
        __half2 vh = *(__half2*)&vu;
        Vth[(d    )*VT_STRH + m] = vh.x;
        Vth[(d + 1)*VT_STRH + m] = vh.y;
    }
    for (int e = tid; e < M_POS; e += 224) {
        float cur = g_pos[h*M_POS + e];
        float prv = (e > 0) ? g_pos[h*M_POS + e - 1] : 0.f;
        poshd[e] = make_float2(cur, prv);
    }
    for (int e = tid; e < NTOK; e += 224)
        midv[e] = (short)((e/36)*121 + ((e/6)%6)*11 + (e%6));
    __syncthreads();

    const __half* qbh = g_qh + (size_t)b*NTOK*CH + h*32;
    __half* obh = g_atth + (size_t)b*NTOK*CH + h*32;
    const uint32_t* mbase = g_mbits + (size_t)g*NTOK*8;
    const float scale = 0.17677669529663687f;  // 32^-0.5

    for (int strip = w; strip < MT; strip += 7) {
        int n0 = strip*16;
        int ra = n0 + grp, rb = ra + 8;
        int ra_c = min(ra, NTOK-1), rb_c = min(rb, NTOK-1);

        // Q A-frags: direct half2 loads
        uint32_t aq[2][4];
        const __half* qa = qbh + (size_t)ra_c*CH;
        const __half* qB = qbh + (size_t)rb_c*CH;
        #pragma unroll
        for (int c = 0; c < 2; c++) {
            aq[c][0] = *(const uint32_t*)&qa[c*16 + 2*tig];
            aq[c][1] = *(const uint32_t*)&qB[c*16 + 2*tig];
            aq[c][2] = *(const uint32_t*)&qa[c*16 + 2*tig + 8];
            aq[c][3] = *(const uint32_t*)&qB[c*16 + 2*tig + 8];
        }

        // row bitmasks (7 words each, broadcast loads)
        uint32_t mba[7], mbb[7];
        {
            const uint32_t* ma = mbase + (size_t)ra_c*8;
            const uint32_t* mb = mbase + (size_t)rb_c*8;
            #pragma unroll
            for (int i = 0; i < 7; i++) { mba[i] = ma[i]; mbb[i] = mb[i]; }
        }

        int nida = midv[ra_c], nidb = midv[rb_c];

        float o[4][4];
        #pragma unroll
        for (int dt = 0; dt < 4; dt++)
            #pragma unroll
            for (int c = 0; c < 4; c++) o[dt][c] = 0.f;
        float sa = 0.f, sb = 0.f;

        #pragma unroll 2
        for (int kt = 0; kt < KT16; kt++) {
            // S tiles = Q K^T
            float s0c[4] = {0.f,0.f,0.f,0.f};
            float s1c[4] = {0.f,0.f,0.f,0.f};
            int key0 = kt*16 + grp;
            #pragma unroll
            for (int c = 0; c < 2; c++) {
                uint32_t b0 = *(const uint32_t*)&Ksh[(key0    )*KS_STRH + c*16 + 2*tig];
                uint32_t b1 = *(const uint32_t*)&Ksh[(key0    )*KS_STRH + c*16 + 2*tig + 8];
                uint32_t d0 = *(const uint32_t*)&Ksh[(key0 + 8)*KS_STRH + c*16 + 2*tig];
                uint32_t d1 = *(const uint32_t*)&Ksh[(key0 + 8)*KS_STRH + c*16 + 2*tig + 8];
                asm volatile(
                    "mma.sync.aligned.m16n8k16.row.col.f32.f16.f16.f32 "
                    "{%0,%1,%2,%3}, {%4,%5,%6,%7}, {%8,%9}, {%0,%1,%2,%3};"
                    : "+f"(s0c[0]), "+f"(s0c[1]), "+f"(s0c[2]), "+f"(s0c[3])
                    : "r"(aq[c][0]), "r"(aq[c][1]), "r"(aq[c][2]), "r"(aq[c][3]),
                      "r"(b0), "r"(b1));
                asm volatile(
                    "mma.sync.aligned.m16n8k16.row.col.f32.f16.f16.f32 "
                    "{%0,%1,%2,%3}, {%4,%5,%6,%7}, {%8,%9}, {%0,%1,%2,%3};"
                    : "+f"(s1c[0]), "+f"(s1c[1]), "+f"(s1c[2]), "+f"(s1c[3])
                    : "r"(aq[c][0]), "r"(aq[c][1]), "r"(aq[c][2]), "r"(aq[c][3]),
                      "r"(d0), "r"(d1));
            }

            // mask bits for this kt (compile-time word index under unroll)
            uint32_t wa = mba[kt >> 1] >> ((kt & 1)*16 + 2*tig);
            uint32_t wb = mbb[kt >> 1] >> ((kt & 1)*16 + 2*tig);

            // bias(paired LUT) + bitmask + exp, accumulate row sums, pack P frags
            uint32_t pa0, pa1, pa2, pa3;
            {
                int m0 = kt*16 + 2*tig;
                int mid0 = midv[m0];
                float2 Pa = poshd[nida - mid0 + 665];   // .x even m, .y odd m
                float2 Pb = poshd[nidb - mid0 + 665];
                float p00 = (wa & 1u)   ? 0.f : __expf(s0c[0]*scale + Pa.x);
                float p01 = (wa & 2u)   ? 0.f : __expf(s0c[1]*scale + Pa.y);
                float p02 = (wb & 1u)   ? 0.f : __expf(s0c[2]*scale + Pb.x);
                float p03 = (wb & 2u)   ? 0.f : __expf(s0c[3]*scale + Pb.y);
                sa += p00 + p01;
                sb += p02 + p03;
                pa0 = pack_h2(p00, p01);
                pa1 = pack_h2(p02, p03);
            }
            if (kt < KT16-1) {
                int m1 = kt*16 + 8 + 2*tig;
                int mid1 = midv[m1];
                float2 Pa = poshd[nida - mid1 + 665];
                float2 Pb = poshd[nidb - mid1 + 665];
                float p10 = (wa & 0x100u) ? 0.f : __expf(s1c[0]*scale + Pa.x);
                float p11 = (wa & 0x200u) ? 0.f : __expf(s1c[1]*scale + Pa.y);
                float p12 = (wb & 0x100u) ? 0.f : __expf(s1c[2]*scale + Pb.x);
                float p13 = (wb & 0x200u) ? 0.f : __expf(s1c[3]*scale + Pb.y);
                sa += p10 + p11;
                sb += p12 + p13;
                pa2 = pack_h2(p10, p11);
                pa3 = pack_h2(p12, p13);
            } else {
                pa2 = 0u; pa3 = 0u;
            }

            // O += P V
            #pragma unroll
            for (int dt = 0; dt < 4; dt++) {
                uint32_t b0 = *(const uint32_t*)&Vth[(dt*8 + grp)*VT_STRH + kt*16 + 2*tig];
                uint32_t b1 = *(const uint32_t*)&Vth[(dt*8 + grp)*VT_STRH + kt*16 + 2*tig + 8];
                asm volatile(
                    "mma.sync.aligned.m16n8k16.row.col.f32.f16.f16.f32 "
                    "{%0,%1,%2,%3}, {%4,%5,%6,%7}, {%8,%9}, {%0,%1,%2,%3};"
                    : "+f"(o[dt][0]), "+f"(o[dt][1]), "+f"(o[dt][2]), "+f"(o[dt][3])
                    : "r"(pa0), "r"(pa1), "r"(pa2), "r"(pa3),
                      "r"(b0), "r"(b1));
            }
        }

        sa += __shfl_xor_sync(0xffffffffu, sa, 1);
        sa += __shfl_xor_sync(0xffffffffu, sa, 2);
        sb += __shfl_xor_sync(0xffffffffu, sb, 1);
        sb += __shfl_xor_sync(0xffffffffu, sb, 2);
        float inva = 1.f / sa, invb = 1.f / sb;

        #pragma unroll
        for (int dt = 0; dt < 4; dt++) {
            int d = dt*8 + 2*tig;
            *(uint32_t*)&obh[(size_t)ra*CH + d] =
                pack_h2(o[dt][0]*inva, o[dt][1]*inva);
            if (rb < NTOK)
                *(uint32_t*)&obh[(size_t)rb*CH + d] =
                    pack_h2(o[dt][2]*invb, o[dt][3]*invb);
        }
    }
}

// ---------------- launch ----------------
extern "C" void kernel_launch(void* const* d_in, const int* in_sizes, int n_in,
                              void* d_out, int out_size)
{
    const float* x     = (const float*)d_in[0];
    const float* y     = (const float*)d_in[1];
    const float* mask  = (const float*)d_in[2];
    const float* Wqkv  = (const float*)d_in[3];
    const float* bqkv  = (const float*)d_in[4];
    const float* Wproj = (const float*)d_in[5];
    const float* bproj = (const float*)d_in[6];
    const float* ppw   = (const float*)d_in[7];
    const float* ppb   = (const float*)d_in[8];
    const float* g1    = (const float*)d_in[9];
    const float* be1   = (const float*)d_in[10];
    const float* w1    = (const float*)d_in[11];
    const float* b1    = (const float*)d_in[12];
    const float* g2    = (const float*)d_in[13];
    const float* be2   = (const float*)d_in[14];
    const float* w2    = (const float*)d_in[15];
    const float* b2    = (const float*)d_in[16];
    const float* g3    = (const float*)d_in[17];
    const float* be3   = (const float*)d_in[18];
    const float* w3    = (const float*)d_in[19];
    const float* b3    = (const float*)d_in[20];
    float* out = (float*)d_out;

    __half *qp, *kvp, *attp, *whp;
    cudaGetSymbolAddress((void**)&qp,   g_qh);
    cudaGetSymbolAddress((void**)&kvp,  g_kvh);
    cudaGetSymbolAddress((void**)&attp, g_atth);
    cudaGetSymbolAddress((void**)&whp,  g_wh);

    // merged preps: mask->bits | weights->fp16 | pos MLP
    prep_kernel<<<PREP_MB + PREP_CB + PREP_PB, 256>>>(
        mask, Wqkv, Wproj, ppw, ppb, g1, be1, w1, b1,
        g2, be2, w2, b2, g3, be3, w3, b3);

    cudaFuncSetAttribute(gemm_f16_big<false,true>,
                         cudaFuncAttributeMaxDynamicSharedMemorySize, GSMEM);
    cudaFuncSetAttribute(gemm_f16_big<true,false>,
                         cudaFuncAttributeMaxDynamicSharedMemorySize, GSMEM);

    // Q = x @ Wq^T + bq  -> half
    gemm_f16_big<false,true><<<NBLK, 256, GSMEM>>>(x, whp, bqkv, qp, CH);
    // KV = y @ Wkv^T + bkv -> half
    gemm_f16_big<false,true><<<NBLK, 256, GSMEM>>>(y, whp + (size_t)CH*CH,
                                                   bqkv + CH, kvp, 2*CH);
    // fused attention (half in, half out; mask via bitmask)
    {
        size_t smem = (size_t)(NKP*KS_STRH + 32*VT_STRH)*2
                    + (size_t)M_POS*8 + (size_t)NTOK*2;
        cudaFuncSetAttribute(attn_tc_kernel, cudaFuncAttributeMaxDynamicSharedMemorySize, (int)smem);
        attn_tc_kernel<<<B_*HEADS, 224, smem>>>();
    }
    // out = att @ Wproj^T + bproj  (half A, float out)
    gemm_f16_big<true,false><<<NBLK, 256, GSMEM>>>(attp, whp + (size_t)3*CH*CH,
                                                   bproj, out, CH);
}

// round 17
// speedup vs baseline: 1.6439x; 1.0139x over previous
#include <cuda_runtime.h>
#include <cuda_fp16.h>
#include <math.h>
#include <stdint.h>

#define B_     256
#define NG_    64
#define HEADS  6
#define CH     192
#define NTOK   216
#define HD     32
#define M_POS  1331
#define PDIM   12
#define MROWS  (B_*NTOK)   // 55296
#define NBLK   (MROWS/128) // 432

// fp16 attention tiling
#define NKP     224        // keys padded to 14*16
#define KS_STRH 40         // K smem row stride in halves: conflict-free frag loads
#define VT2_STR 240        // permuted V^T row stride in halves: 60 8B-units, conflict-free LDS.64
#define KT16    14         // 16-key tiles
#define MT      14         // m16 query strips

// fp16 GEMM (A-resident, whole-W-block) tiling
#define AHS     200        // SMEM row stride in halves (banks 4*grp+tig, conflict-free)
#define GSMEM   ((128*AHS + 64*AHS)*2)   // 76800 B

// prep kernel block partition
#define PREP_MB 1728       // mask_bits blocks
#define PREP_CB 144        // conv_w blocks
#define PREP_PB 6          // pos_mlp blocks

#define LOG2E 1.4426950408889634f

// ---------------- scratch (all intermediates fp16) ----------------
__device__ __half   g_qh   [(size_t)MROWS*CH];
__device__ __half   g_kvh  [(size_t)MROWS*2*CH];
__device__ __half   g_atth [(size_t)MROWS*CH];
__device__ __half   g_wh   [(size_t)4*CH*CH];
__device__ float    g_pos  [HEADS*M_POS];
__device__ uint32_t g_mbits[(size_t)NG_*NTOK*8];  // mask bitmask: 1 = masked

__device__ __forceinline__ uint32_t pack_h2(float a, float b) {
    __half2 h = __floats2half2_rn(a, b);
    return *(uint32_t*)&h;
}
__device__ __forceinline__ float ex2(float x) {
    float r;
    asm("ex2.approx.f32 %0, %1;" : "=f"(r) : "f"(x));
    return r;
}

// ---------------- tiny dynamic position-bias MLP helper ----------------
__device__ __forceinline__ void ln12(float* t, const float* g, const float* b) {
    float mu = 0.f;
    #pragma unroll
    for (int i = 0; i < PDIM; i++) mu += t[i];
    mu *= (1.f/PDIM);
    float v = 0.f;
    #pragma unroll
    for (int i = 0; i < PDIM; i++) { float d = t[i]-mu; v += d*d; }
    v *= (1.f/PDIM);
    float inv = rsqrtf(v + 1e-5f);
    #pragma unroll
    for (int i = 0; i < PDIM; i++) t[i] = (t[i]-mu)*inv*g[i] + b[i];
}

// ---------------- merged prep kernel: mask_bits | conv_w | pos_mlp ----------------
__global__ void prep_kernel(
    const float* __restrict__ mask,
    const float* __restrict__ Wqkv, const float* __restrict__ Wproj,
    const float* __restrict__ ppw, const float* __restrict__ ppb,
    const float* __restrict__ g1,  const float* __restrict__ be1,
    const float* __restrict__ w1,  const float* __restrict__ b1,
    const float* __restrict__ g2,  const float* __restrict__ be2,
    const float* __restrict__ w2,  const float* __restrict__ b2,
    const float* __restrict__ g3,  const float* __restrict__ be3,
    const float* __restrict__ w3,  const float* __restrict__ b3)
{
    int bi = blockIdx.x;
    if (bi < PREP_MB) {
        int row  = (bi*256 + (int)threadIdx.x) >> 5;
        int lane = threadIdx.x & 31;
        if (row >= NG_*NTOK) return;
        const float* r = mask + (size_t)row*NTOK;
        #pragma unroll
        for (int i = 0; i < 7; i++) {
            int m = i*32 + lane;
            bool bit = (m < NTOK) && (r[m] < -1.f);
            uint32_t wv = __ballot_sync(0xffffffffu, bit);
            if (lane == 0) g_mbits[(size_t)row*8 + i] = wv;
        }
    } else if (bi < PREP_MB + PREP_CB) {
        int i = ((bi - PREP_MB)*256 + (int)threadIdx.x) * 4;
        const int QKV = 3*CH*CH;
        const int TOT = 4*CH*CH;
        if (i >= TOT) return;
        float4 v = (i < QKV) ? *(const float4*)(Wqkv + i)
                             : *(const float4*)(Wproj + (i - QKV));
        uint2 p = make_uint2(pack_h2(v.x, v.y), pack_h2(v.z, v.w));
        *(uint2*)&g_wh[i] = p;
    } else {
        int m = (bi - PREP_MB - PREP_CB)*256 + (int)threadIdx.x;
        if (m >= M_POS) return;
        float c0 = (float)(m/121 - 5);
        float c1 = (float)((m/11)%11 - 5);
        float c2 = (float)(m%11 - 5);
        float t[PDIM], u[PDIM];
        #pragma unroll
        for (int i = 0; i < PDIM; i++)
            t[i] = ppw[i*3+0]*c0 + ppw[i*3+1]*c1 + ppw[i*3+2]*c2 + ppb[i];
        ln12(t, g1, be1);
        #pragma unroll
        for (int i = 0; i < PDIM; i++) {
            float acc = b1[i];
            #pragma unroll
            for (int j = 0; j < PDIM; j++) acc += w1[i*PDIM+j]*fmaxf(t[j],0.f);
            u[i] = acc;
        }
        ln12(u, g2, be2);
        #pragma unroll
        for (int i = 0; i < PDIM; i++) {
            float acc = b2[i];
            #pragma unroll
            for (int j = 0; j < PDIM; j++) acc += w2[i*PDIM+j]*fmaxf(u[j],0.f);
            t[i] = acc;
        }
        ln12(t, g3, be3);
        #pragma unroll
        for (int h = 0; h < HEADS; h++) {
            float acc = b3[h];
            #pragma unroll
            for (int j = 0; j < PDIM; j++) acc += w3[h*PDIM+j]*fmaxf(t[j],0.f);
            g_pos[h*M_POS + m] = acc;
        }
    }
}

// ---------------- FP16 tensor-core GEMM: A-resident, whole-W-block, reg prefetch ----------------
template<bool A_HALF, bool OUT_HALF>
__global__ __launch_bounds__(256)
void gemm_f16_big(const void* __restrict__ Ain, const __half* __restrict__ Wh,
                  const float* __restrict__ bias, void* __restrict__ Cout, int Ndim)
{
    extern __shared__ __half sg[];
    __half* Ah = sg;                 // [128][AHS]
    __half* Ws = Ah + 128*AHS;       // [64][AHS]

    int tid  = threadIdx.x;
    int w    = tid >> 5, lane = tid & 31;
    int grp  = lane >> 2, tig = lane & 3;
    int wm   = (w >> 1) * 32;
    int wn   = (w & 1) * 32;
    int m0   = blockIdx.x * 128;

    if (A_HALF) {
        const __half* Af = (const __half*)Ain + (size_t)m0*CH;
        #pragma unroll
        for (int i = 0; i < 24; i++) {
            int idx = i*256 + tid;
            int row = idx/48, c4 = idx%48;
            uint2 v = *(const uint2*)(Af + (size_t)row*CH + c4*4);
            *(uint2*)&Ah[row*AHS + c4*4] = v;
        }
    } else {
        const float* Af = (const float*)Ain + (size_t)m0*CH;
        #pragma unroll
        for (int i = 0; i < 24; i++) {
            int idx = i*256 + tid;
            int row = idx/48, c4 = idx%48;
            float4 v = *(const float4*)(Af + (size_t)row*CH + c4*4);
            uint2 p = make_uint2(pack_h2(v.x, v.y), pack_h2(v.z, v.w));
            *(uint2*)&Ah[row*AHS + c4*4] = p;
        }
    }

    const uint32_t* Ahw = (const uint32_t*)Ah;
    uint32_t* Wsw = (uint32_t*)Ws;
    int nbc = Ndim >> 6;

    uint4 wR[6];
    #pragma unroll
    for (int i = 0; i < 6; i++) {
        int idx = i*256 + tid;
        int row = idx/24, c8 = idx%24;
        wR[i] = *(const uint4*)(Wh + (size_t)row*CH + c8*8);
    }

    for (int nb = 0; nb < nbc; nb++) {
        #pragma unroll
        for (int i = 0; i < 6; i++) {
            int idx = i*256 + tid;
            int row = idx/24, c8 = idx%24;
            *(uint4*)&Ws[row*AHS + c8*8] = wR[i];
        }
        __syncthreads();

        if (nb + 1 < nbc) {
            const __half* Wb = Wh + (size_t)(nb+1)*64*CH;
            #pragma unroll
            for (int i = 0; i < 6; i++) {
                int idx = i*256 + tid;
                int row = idx/24, c8 = idx%24;
                wR[i] = *(const uint4*)(Wb + (size_t)row*CH + c8*8);
            }
        }

        float acc[2][4][4];
        #pragma unroll
        for (int i = 0; i < 2; i++)
            #pragma unroll
            for (int j = 0; j < 4; j++)
                #pragma unroll
                for (int c = 0; c < 4; c++) acc[i][j][c] = 0.f;

        #pragma unroll
        for (int st = 0; st < 12; st++) {
            int ko = st*8;
            uint32_t af[2][4], bf[4][2];
            #pragma unroll
            for (int mf = 0; mf < 2; mf++) {
                int r = wm + mf*16 + grp;
                af[mf][0] = Ahw[(r    )*(AHS/2) + ko + tig];
                af[mf][1] = Ahw[(r + 8)*(AHS/2) + ko + tig];
                af[mf][2] = Ahw[(r    )*(AHS/2) + ko + tig + 4];
                af[mf][3] = Ahw[(r + 8)*(AHS/2) + ko + tig + 4];
            }
            #pragma unroll
            for (int nf = 0; nf < 4; nf++) {
                int n = wn + nf*8 + grp;
                bf[nf][0] = Wsw[n*(AHS/2) + ko + tig];
                bf[nf][1] = Wsw[n*(AHS/2) + ko + tig + 4];
            }
            #pragma unroll
            for (int mf = 0; mf < 2; mf++)
                #pragma unroll
                for (int nf = 0; nf < 4; nf++) {
                    asm volatile(
                        "mma.sync.aligned.m16n8k16.row.col.f32.f16.f16.f32 "
                        "{%0,%1,%2,%3}, {%4,%5,%6,%7}, {%8,%9}, {%0,%1,%2,%3};"
                        : "+f"(acc[mf][nf][0]), "+f"(acc[mf][nf][1]),
                          "+f"(acc[mf][nf][2]), "+f"(acc[mf][nf][3])
                        : "r"(af[mf][0]), "r"(af[mf][1]), "r"(af[mf][2]), "r"(af[mf][3]),
                          "r"(bf[nf][0]), "r"(bf[nf][1]));
                }
        }

        int n0 = nb*64;
        #pragma unroll
        for (int mf = 0; mf < 2; mf++) {
            #pragma unroll
            for (int nf = 0; nf < 4; nf++) {
                int col = n0 + wn + nf*8 + 2*tig;
                float bx = bias[col], by = bias[col+1];
                int r0 = m0 + wm + mf*16 + grp;
                if (OUT_HALF) {
                    __half* Co = (__half*)Cout;
                    *(uint32_t*)&Co[(size_t)r0*Ndim + col] =
                        pack_h2(acc[mf][nf][0] + bx, acc[mf][nf][1] + by);
                    *(uint32_t*)&Co[(size_t)(r0+8)*Ndim + col] =
                        pack_h2(acc[mf][nf][2] + bx, acc[mf][nf][3] + by);
                } else {
                    float* Co = (float*)Cout;
                    *(float2*)&Co[(size_t)r0*Ndim + col] =
                        make_float2(acc[mf][nf][0] + bx, acc[mf][nf][1] + by);
                    *(float2*)&Co[(size_t)(r0+8)*Ndim + col] =
                        make_float2(acc[mf][nf][2] + bx, acc[mf][nf][3] + by);
                }
            }
        }
        __syncthreads();
    }
}

// ---------------- fp16 tensor-core fused attention ----------------
// 224 threads: 7 warps x 2 strips. Permuted V (LDS.64 frags), ex2-folded softmax,
// pre-shifted mask words with constant bit tests.
__global__ __launch_bounds__(224)
void attn_tc_kernel()
{
    extern __shared__ __half smh[];
    __half* Ksh  = smh;                          // [224][40] half
    __half* Vt2  = Ksh + NKP*KS_STRH;            // [32][240] half, k16-permuted V^T
    float2* poshd = (float2*)(Vt2 + 32*VT2_STR); // [1331] (pos[a], pos[a-1]) * log2e
    short*  midv  = (short*)(poshd + M_POS);     // [216] pid3 LUT

    int bh = blockIdx.x;
    int b  = bh / HEADS, h = bh % HEADS;
    int g  = b & (NG_-1);
    int tid = threadIdx.x;
    int w = tid >> 5, lane = tid & 31;
    int grp = lane >> 2, tig = lane & 3;

    const __half* kvbh = g_kvh + (size_t)b*NTOK*(2*CH);
    for (int e = tid; e < NKP*16; e += 224) {
        int m = e >> 4, d = (e & 15)*2;
        uint32_t ku = 0u, vu = 0u;
        if (m < NTOK) {
            ku = *(const uint32_t*)&kvbh[(size_t)m*(2*CH) + h*32 + d];
            vu = *(const uint32_t*)&kvbh[(size_t)m*(2*CH) + CH + h*32 + d];
        }
        *(uint32_t*)&Ksh[m*KS_STRH + d] = ku;
        __half2 vh = *(__half2*)&vu;
        // permuted V layout: per (row d, kt) 16 keys as [k0 k1 k8 k9 | k2 k3 k10 k11 | ...]
        int offm = (m >> 4)*16 + ((m & 7) >> 1)*4 + ((m >> 3) & 1)*2 + (m & 1);
        Vt2[(d    )*VT2_STR + offm] = vh.x;
        Vt2[(d + 1)*VT2_STR + offm] = vh.y;
    }
    for (int e = tid; e < M_POS; e += 224) {
        float cur = g_pos[h*M_POS + e] * LOG2E;
        float prv = (e > 0) ? g_pos[h*M_POS + e - 1] * LOG2E : 0.f;
        poshd[e] = make_float2(cur, prv);
    }
    for (int e = tid; e < NTOK; e += 224)
        midv[e] = (short)((e/36)*121 + ((e/6)%6)*11 + (e%6));
    __syncthreads();

    const __half* qbh = g_qh + (size_t)b*NTOK*CH + h*32;
    __half* obh = g_atth + (size_t)b*NTOK*CH + h*32;
    const uint32_t* mbase = g_mbits + (size_t)g*NTOK*8;
    const float scale2 = 0.17677669529663687f * LOG2E;  // 32^-0.5 * log2(e)

    for (int strip = w; strip < MT; strip += 7) {
        int n0 = strip*16;
        int ra = n0 + grp, rb = ra + 8;
        int ra_c = min(ra, NTOK-1), rb_c = min(rb, NTOK-1);

        // Q A-frags: direct half2 loads
        uint32_t aq[2][4];
        const __half* qa = qbh + (size_t)ra_c*CH;
        const __half* qB = qbh + (size_t)rb_c*CH;
        #pragma unroll
        for (int c = 0; c < 2; c++) {
            aq[c][0] = *(const uint32_t*)&qa[c*16 + 2*tig];
            aq[c][1] = *(const uint32_t*)&qB[c*16 + 2*tig];
            aq[c][2] = *(const uint32_t*)&qa[c*16 + 2*tig + 8];
            aq[c][3] = *(const uint32_t*)&qB[c*16 + 2*tig + 8];
        }

        // row bitmasks pre-shifted by 2*tig -> constant bit tests in the loop
        uint32_t mba[7], mbb[7];
        {
            const uint32_t* ma = mbase + (size_t)ra_c*8;
            const uint32_t* mb = mbase + (size_t)rb_c*8;
            int sh = 2*tig;
            #pragma unroll
            for (int i = 0; i < 7; i++) { mba[i] = ma[i] >> sh; mbb[i] = mb[i] >> sh; }
        }

        int nida = midv[ra_c], nidb = midv[rb_c];

        float o[4][4];
        #pragma unroll
        for (int dt = 0; dt < 4; dt++)
            #pragma unroll
            for (int c = 0; c < 4; c++) o[dt][c] = 0.f;
        float sa = 0.f, sb = 0.f;

        #pragma unroll 2
        for (int kt = 0; kt < KT16; kt++) {
            // S tiles = Q K^T
            float s0c[4] = {0.f,0.f,0.f,0.f};
            float s1c[4] = {0.f,0.f,0.f,0.f};
            int key0 = kt*16 + grp;
            #pragma unroll
            for (int c = 0; c < 2; c++) {
                uint32_t b0 = *(const uint32_t*)&Ksh[(key0    )*KS_STRH + c*16 + 2*tig];
                uint32_t b1 = *(const uint32_t*)&Ksh[(key0    )*KS_STRH + c*16 + 2*tig + 8];
                uint32_t d0 = *(const uint32_t*)&Ksh[(key0 + 8)*KS_STRH + c*16 + 2*tig];
                uint32_t d1 = *(const uint32_t*)&Ksh[(key0 + 8)*KS_STRH + c*16 + 2*tig + 8];
                asm volatile(
                    "mma.sync.aligned.m16n8k16.row.col.f32.f16.f16.f32 "
                    "{%0,%1,%2,%3}, {%4,%5,%6,%7}, {%8,%9}, {%0,%1,%2,%3};"
                    : "+f"(s0c[0]), "+f"(s0c[1]), "+f"(s0c[2]), "+f"(s0c[3])
                    : "r"(aq[c][0]), "r"(aq[c][1]), "r"(aq[c][2]), "r"(aq[c][3]),
                      "r"(b0), "r"(b1));
                asm volatile(
                    "mma.sync.aligned.m16n8k16.row.col.f32.f16.f16.f32 "
                    "{%0,%1,%2,%3}, {%4,%5,%6,%7}, {%8,%9}, {%0,%1,%2,%3};"
                    : "+f"(s1c[0]), "+f"(s1c[1]), "+f"(s1c[2]), "+f"(s1c[3])
                    : "r"(aq[c][0]), "r"(aq[c][1]), "r"(aq[c][2]), "r"(aq[c][3]),
                      "r"(d0), "r"(d1));
            }

            uint32_t wa = mba[kt >> 1];
            uint32_t wb = mbb[kt >> 1];
            uint32_t blo = (kt & 1) ? 0x10000u : 1u;   // compile-time under unroll 2

            // bias(paired ex2 LUT) + bitmask + ex2, accumulate row sums, pack P frags
            uint32_t pa0, pa1, pa2, pa3;
            {
                int m0 = kt*16 + 2*tig;
                int mid0 = midv[m0];
                float2 Pa = poshd[nida - mid0 + 665];   // .x even m, .y odd m
                float2 Pb = poshd[nidb - mid0 + 665];
                float p00 = (wa & blo)      ? 0.f : ex2(s0c[0]*scale2 + Pa.x);
                float p01 = (wa & (blo<<1)) ? 0.f : ex2(s0c[1]*scale2 + Pa.y);
                float p02 = (wb & blo)      ? 0.f : ex2(s0c[2]*scale2 + Pb.x);
                float p03 = (wb & (blo<<1)) ? 0.f : ex2(s0c[3]*scale2 + Pb.y);
                sa += p00 + p01;
                sb += p02 + p03;
                pa0 = pack_h2(p00, p01);
                pa1 = pack_h2(p02, p03);
            }
            if (kt < KT16-1) {
                int m1 = kt*16 + 8 + 2*tig;
                int mid1 = midv[m1];
                float2 Pa = poshd[nida - mid1 + 665];
                float2 Pb = poshd[nidb - mid1 + 665];
                float p10 = (wa & (blo<<8)) ? 0.f : ex2(s1c[0]*scale2 + Pa.x);
                float p11 = (wa & (blo<<9)) ? 0.f : ex2(s1c[1]*scale2 + Pa.y);
                float p12 = (wb & (blo<<8)) ? 0.f : ex2(s1c[2]*scale2 + Pb.x);
                float p13 = (wb & (blo<<9)) ? 0.f : ex2(s1c[3]*scale2 + Pb.y);
                sa += p10 + p11;
                sb += p12 + p13;
                pa2 = pack_h2(p10, p11);
                pa3 = pack_h2(p12, p13);
            } else {
                pa2 = 0u; pa3 = 0u;
            }

            // O += P V  (permuted V: one LDS.64 per dt)
            #pragma unroll
            for (int dt = 0; dt < 4; dt++) {
                uint2 vv = *(const uint2*)&Vt2[(dt*8 + grp)*VT2_STR + kt*16 + tig*4];
                asm volatile(
                    "mma.sync.aligned.m16n8k16.row.col.f32.f16.f16.f32 "
                    "{%0,%1,%2,%3}, {%4,%5,%6,%7}, {%8,%9}, {%0,%1,%2,%3};"
                    : "+f"(o[dt][0]), "+f"(o[dt][1]), "+f"(o[dt][2]), "+f"(o[dt][3])
                    : "r"(pa0), "r"(pa1), "r"(pa2), "r"(pa3),
                      "r"(vv.x), "r"(vv.y));
            }
        }

        sa += __shfl_xor_sync(0xffffffffu, sa, 1);
        sa += __shfl_xor_sync(0xffffffffu, sa, 2);
        sb += __shfl_xor_sync(0xffffffffu, sb, 1);
        sb += __shfl_xor_sync(0xffffffffu, sb, 2);
        float inva = 1.f / sa, invb = 1.f / sb;

        #pragma unroll
        for (int dt = 0; dt < 4; dt++) {
            int d = dt*8 + 2*tig;
            *(uint32_t*)&obh[(size_t)ra*CH + d] =
                pack_h2(o[dt][0]*inva, o[dt][1]*inva);
            if (rb < NTOK)
                *(uint32_t*)&obh[(size_t)rb*CH + d] =
                    pack_h2(o[dt][2]*invb, o[dt][3]*invb);
        }
    }
}

// ---------------- launch ----------------
extern "C" void kernel_launch(void* const* d_in, const int* in_sizes, int n_in,
                              void* d_out, int out_size)
{
    const float* x     = (const float*)d_in[0];
    const float* y     = (const float*)d_in[1];
    const float* mask  = (const float*)d_in[2];
    const float* Wqkv  = (const float*)d_in[3];
    const float* bqkv  = (const float*)d_in[4];
    const float* Wproj = (const float*)d_in[5];
    const float* bproj = (const float*)d_in[6];
    const float* ppw   = (const float*)d_in[7];
    const float* ppb   = (const float*)d_in[8];
    const float* g1    = (const float*)d_in[9];
    const float* be1   = (const float*)d_in[10];
    const float* w1    = (const float*)d_in[11];
    const float* b1    = (const float*)d_in[12];
    const float* g2    = (const float*)d_in[13];
    const float* be2   = (const float*)d_in[14];
    const float* w2    = (const float*)d_in[15];
    const float* b2    = (const float*)d_in[16];
    const float* g3    = (const float*)d_in[17];
    const float* be3   = (const float*)d_in[18];
    const float* w3    = (const float*)d_in[19];
    const float* b3    = (const float*)d_in[20];
    float* out = (float*)d_out;

    __half *qp, *kvp, *attp, *whp;
    cudaGetSymbolAddress((void**)&qp,   g_qh);
    cudaGetSymbolAddress((void**)&kvp,  g_kvh);
    cudaGetSymbolAddress((void**)&attp, g_atth);
    cudaGetSymbolAddress((void**)&whp,  g_wh);

    // merged preps: mask->bits | weights->fp16 | pos MLP
    prep_kernel<<<PREP_MB + PREP_CB + PREP_PB, 256>>>(
        mask, Wqkv, Wproj, ppw, ppb, g1, be1, w1, b1,
        g2, be2, w2, b2, g3, be3, w3, b3);

    cudaFuncSetAttribute(gemm_f16_big<false,true>,
                         cudaFuncAttributeMaxDynamicSharedMemorySize, GSMEM);
    cudaFuncSetAttribute(gemm_f16_big<true,false>,
                         cudaFuncAttributeMaxDynamicSharedMemorySize, GSMEM);

    // Q = x @ Wq^T + bq  -> half
    gemm_f16_big<false,true><<<NBLK, 256, GSMEM>>>(x, whp, bqkv, qp, CH);
    // KV = y @ Wkv^T + bkv -> half
    gemm_f16_big<false,true><<<NBLK, 256, GSMEM>>>(y, whp + (size_t)CH*CH,
                                                   bqkv + CH, kvp, 2*CH);
    // fused attention
    {
        size_t smem = (size_t)(NKP*KS_STRH + 32*VT2_STR)*2
                    + (size_t)M_POS*8 + (size_t)NTOK*2;
        cudaFuncSetAttribute(attn_tc_kernel, cudaFuncAttributeMaxDynamicSharedMemorySize, (int)smem);
        attn_tc_kernel<<<B_*HEADS, 224, smem>>>();
    }
    // out = att @ Wproj^T + bproj  (half A, float out)
    gemm_f16_big<true,false><<<NBLK, 256, GSMEM>>>(attp, whp + (size_t)3*CH*CH,
                                                   bproj, out, CH);
}